// round 2
// baseline (speedup 1.0000x reference)
#include <cuda_runtime.h>
#include <stdint.h>

#define N_NODES 1000000
#define F 16

// Scratch (allocation-free rule: __device__ globals)
__device__ float g_h[(size_t)N_NODES * F];   // h = x @ W
__device__ float g_deg[N_NODES];             // edge-count degree (no self loop)
__device__ float g_dinv[N_NODES];            // rsqrt(deg + 1)

// ---------------------------------------------------------------------------
// K0: zero the degree accumulator
// ---------------------------------------------------------------------------
__global__ void k_zero_deg(int n) {
    int i = blockIdx.x * blockDim.x + threadIdx.x;
    if (i < n) g_deg[i] = 0.0f;
}

// ---------------------------------------------------------------------------
// K1: degree on target nodes. 4M float RED into a 4MB L2-resident array.
// ---------------------------------------------------------------------------
__global__ void k_degree(const int* __restrict__ col, int E, int n) {
    int e = blockIdx.x * blockDim.x + threadIdx.x;
    if (e < E) {
        int c = col[e];
        if ((unsigned)c < (unsigned)n)
            atomicAdd(&g_deg[c], 1.0f);  // compiles to REDG (result unused)
    }
}

// ---------------------------------------------------------------------------
// K2: per-node fused kernel:
//   h[n]    = x[n] @ W              -> g_h
//   dinv[n] = rsqrt(deg[n] + 1)     -> g_dinv
//   out[n]  = h[n]*dinv^2 + b       (self-loop term + bias; initializes d_out)
// ---------------------------------------------------------------------------
__global__ void __launch_bounds__(256)
k_h_self(const float4* __restrict__ x4, const float* __restrict__ W,
         const float* __restrict__ b, float4* __restrict__ out4, int n) {
    __shared__ float sW[F * F];
    __shared__ float sb[F];
    if (threadIdx.x < F * F) sW[threadIdx.x] = W[threadIdx.x];
    if (threadIdx.x < F)     sb[threadIdx.x] = b[threadIdx.x];
    __syncthreads();

    int i = blockIdx.x * blockDim.x + threadIdx.x;
    if (i >= n) return;

    float4 xv0 = x4[(size_t)i * 4 + 0];
    float4 xv1 = x4[(size_t)i * 4 + 1];
    float4 xv2 = x4[(size_t)i * 4 + 2];
    float4 xv3 = x4[(size_t)i * 4 + 3];
    float xr[F] = {xv0.x, xv0.y, xv0.z, xv0.w,
                   xv1.x, xv1.y, xv1.z, xv1.w,
                   xv2.x, xv2.y, xv2.z, xv2.w,
                   xv3.x, xv3.y, xv3.z, xv3.w};

    float acc[F];
#pragma unroll
    for (int j = 0; j < F; j++) acc[j] = 0.0f;
#pragma unroll
    for (int k = 0; k < F; k++) {
        float xk = xr[k];
#pragma unroll
        for (int j = 0; j < F; j++) acc[j] = fmaf(xk, sW[k * F + j], acc[j]);
    }

    // store h
    float4* hp = reinterpret_cast<float4*>(g_h + (size_t)i * F);
#pragma unroll
    for (int q = 0; q < 4; q++) {
        hp[q] = make_float4(acc[q * 4 + 0], acc[q * 4 + 1],
                            acc[q * 4 + 2], acc[q * 4 + 3]);
    }

    float deg = g_deg[i] + 1.0f;           // +1 self loop
    float dinv = rsqrtf(deg);
    g_dinv[i] = dinv;
    float s = dinv * dinv;

#pragma unroll
    for (int q = 0; q < 4; q++) {
        out4[(size_t)i * 4 + q] = make_float4(
            fmaf(acc[q * 4 + 0], s, sb[q * 4 + 0]),
            fmaf(acc[q * 4 + 1], s, sb[q * 4 + 1]),
            fmaf(acc[q * 4 + 2], s, sb[q * 4 + 2]),
            fmaf(acc[q * 4 + 3], s, sb[q * 4 + 3]));
    }
}

// ---------------------------------------------------------------------------
// K3: edge scatter. Per edge: gather h[row] (4x LDG.128), scale by
// dinv[row]*dinv[col], vector-reduce into out[col] via red.global.add.v4.f32.
// ---------------------------------------------------------------------------
__global__ void __launch_bounds__(256)
k_edge(const int* __restrict__ ei, float* __restrict__ out, int E, int n) {
    int e = blockIdx.x * blockDim.x + threadIdx.x;
    if (e >= E) return;

    int r = ei[e];                 // src
    int c = ei[(size_t)E + e];     // dst
    if ((unsigned)r >= (unsigned)n || (unsigned)c >= (unsigned)n) return;

    float norm = g_dinv[r] * g_dinv[c];

    const float4* hp = reinterpret_cast<const float4*>(g_h + (size_t)r * F);
    float* op = out + (size_t)c * F;

#pragma unroll
    for (int q = 0; q < 4; q++) {
        float4 v = __ldg(&hp[q]);
        asm volatile(
            "red.global.add.v4.f32 [%0], {%1, %2, %3, %4};"
            :: "l"(op + q * 4),
               "f"(v.x * norm), "f"(v.y * norm), "f"(v.z * norm), "f"(v.w * norm)
            : "memory");
    }
}

// ---------------------------------------------------------------------------
// launch
// ---------------------------------------------------------------------------
extern "C" void kernel_launch(void* const* d_in, const int* in_sizes, int n_in,
                              void* d_out, int out_size) {
    const float* x   = (const float*)d_in[0];
    const int*   ei  = (const int*)d_in[1];    // int32! (JAX x64 disabled)
    const float* W   = (const float*)d_in[2];
    const float* b   = (const float*)d_in[3];
    float*       out = (float*)d_out;

    int n = in_sizes[0] / F;       // 1,000,000 nodes
    int E = in_sizes[1] / 2;       // 4,000,000 edges

    const int T = 256;

    k_zero_deg<<<(n + T - 1) / T, T>>>(n);
    k_degree<<<(E + T - 1) / T, T>>>(ei + (size_t)E, E, n);
    k_h_self<<<(n + T - 1) / T, T>>>((const float4*)x, W, b, (float4*)out, n);
    k_edge<<<(E + T - 1) / T, T>>>(ei, out, E, n);
}

// round 3
// speedup vs baseline: 1.1345x; 1.1345x over previous
#include <cuda_runtime.h>
#include <cuda_fp16.h>
#include <stdint.h>

#define N_NODES 1000000
#define F 16

// Scratch (allocation-free rule: __device__ globals)
__device__ __half g_h[(size_t)N_NODES * F];  // h = x @ W   (fp16, 32MB)
__device__ float  g_deg[N_NODES];            // edge-count degree (no self loop)
__device__ float  g_dinv[N_NODES];           // rsqrt(deg + 1)

// ---------------------------------------------------------------------------
// K0: zero the degree accumulator
// ---------------------------------------------------------------------------
__global__ void k_zero_deg(int n) {
    int i = blockIdx.x * blockDim.x + threadIdx.x;
    if (i < n) g_deg[i] = 0.0f;
}

// ---------------------------------------------------------------------------
// K1: degree on target nodes. 4M float RED into a 4MB L2-resident array.
// ---------------------------------------------------------------------------
__global__ void k_degree(const int* __restrict__ col, int E, int n) {
    int e = blockIdx.x * blockDim.x + threadIdx.x;
    if (e < E) {
        int c = col[e];
        if ((unsigned)c < (unsigned)n)
            atomicAdd(&g_deg[c], 1.0f);  // REDG (result unused)
    }
}

// ---------------------------------------------------------------------------
// K2: per-node fused kernel:
//   h[n]    = x[n] @ W   -> g_h (fp16)
//   dinv[n] = rsqrt(deg[n] + 1)
//   out[n]  = h[n]*dinv^2 + b   (self-loop in fp32 + bias; initializes d_out)
// ---------------------------------------------------------------------------
__global__ void __launch_bounds__(256)
k_h_self(const float4* __restrict__ x4, const float* __restrict__ W,
         const float* __restrict__ b, float4* __restrict__ out4, int n) {
    __shared__ float sW[F * F];
    __shared__ float sb[F];
    if (threadIdx.x < F * F) sW[threadIdx.x] = W[threadIdx.x];
    if (threadIdx.x < F)     sb[threadIdx.x] = b[threadIdx.x];
    __syncthreads();

    int i = blockIdx.x * blockDim.x + threadIdx.x;
    if (i >= n) return;

    float4 xv0 = x4[(size_t)i * 4 + 0];
    float4 xv1 = x4[(size_t)i * 4 + 1];
    float4 xv2 = x4[(size_t)i * 4 + 2];
    float4 xv3 = x4[(size_t)i * 4 + 3];
    float xr[F] = {xv0.x, xv0.y, xv0.z, xv0.w,
                   xv1.x, xv1.y, xv1.z, xv1.w,
                   xv2.x, xv2.y, xv2.z, xv2.w,
                   xv3.x, xv3.y, xv3.z, xv3.w};

    float acc[F];
#pragma unroll
    for (int j = 0; j < F; j++) acc[j] = 0.0f;
#pragma unroll
    for (int k = 0; k < F; k++) {
        float xk = xr[k];
#pragma unroll
        for (int j = 0; j < F; j++) acc[j] = fmaf(xk, sW[k * F + j], acc[j]);
    }

    // store h as fp16: 16 halves = 2x 16B stores
    uint4 hpk[2];
    __half2* hh = reinterpret_cast<__half2*>(&hpk[0]);
#pragma unroll
    for (int q = 0; q < 8; q++)
        hh[q] = __floats2half2_rn(acc[2 * q], acc[2 * q + 1]);
    uint4* hp = reinterpret_cast<uint4*>(g_h + (size_t)i * F);
    hp[0] = hpk[0];
    hp[1] = hpk[1];

    float deg = g_deg[i] + 1.0f;  // +1 self loop
    float dinv = rsqrtf(deg);
    g_dinv[i] = dinv;
    float s = dinv * dinv;

#pragma unroll
    for (int q = 0; q < 4; q++) {
        out4[(size_t)i * 4 + q] = make_float4(
            fmaf(acc[q * 4 + 0], s, sb[q * 4 + 0]),
            fmaf(acc[q * 4 + 1], s, sb[q * 4 + 1]),
            fmaf(acc[q * 4 + 2], s, sb[q * 4 + 2]),
            fmaf(acc[q * 4 + 3], s, sb[q * 4 + 3]));
    }
}

// ---------------------------------------------------------------------------
// K3: edge scatter. Per edge: gather h[row] (2x LDG.128 of fp16), scale by
// dinv[row]*dinv[col] in fp32, vector-reduce into out[col] via
// red.global.add.v4.f32 (4 vector REDG per edge).
// ---------------------------------------------------------------------------
__global__ void __launch_bounds__(256)
k_edge(const int* __restrict__ ei, float* __restrict__ out, int E, int n) {
    int e = blockIdx.x * blockDim.x + threadIdx.x;
    if (e >= E) return;

    int r = ei[e];              // src
    int c = ei[(size_t)E + e];  // dst
    if ((unsigned)r >= (unsigned)n || (unsigned)c >= (unsigned)n) return;

    float norm = g_dinv[r] * g_dinv[c];

    const uint4* hp = reinterpret_cast<const uint4*>(g_h + (size_t)r * F);
    uint4 pk0 = __ldg(&hp[0]);
    uint4 pk1 = __ldg(&hp[1]);

    float v[F];
    {
        const __half2* hh0 = reinterpret_cast<const __half2*>(&pk0);
        const __half2* hh1 = reinterpret_cast<const __half2*>(&pk1);
#pragma unroll
        for (int q = 0; q < 4; q++) {
            float2 f = __half22float2(hh0[q]);
            v[2 * q] = f.x; v[2 * q + 1] = f.y;
        }
#pragma unroll
        for (int q = 0; q < 4; q++) {
            float2 f = __half22float2(hh1[q]);
            v[8 + 2 * q] = f.x; v[8 + 2 * q + 1] = f.y;
        }
    }

    float* op = out + (size_t)c * F;
#pragma unroll
    for (int q = 0; q < 4; q++) {
        asm volatile(
            "red.global.add.v4.f32 [%0], {%1, %2, %3, %4};"
            :: "l"(op + q * 4),
               "f"(v[q * 4 + 0] * norm), "f"(v[q * 4 + 1] * norm),
               "f"(v[q * 4 + 2] * norm), "f"(v[q * 4 + 3] * norm)
            : "memory");
    }
}

// ---------------------------------------------------------------------------
// launch
// ---------------------------------------------------------------------------
extern "C" void kernel_launch(void* const* d_in, const int* in_sizes, int n_in,
                              void* d_out, int out_size) {
    const float* x   = (const float*)d_in[0];
    const int*   ei  = (const int*)d_in[1];  // int32 (JAX x64 disabled)
    const float* W   = (const float*)d_in[2];
    const float* b   = (const float*)d_in[3];
    float*       out = (float*)d_out;

    int n = in_sizes[0] / F;   // 1,000,000 nodes
    int E = in_sizes[1] / 2;   // 4,000,000 edges

    const int T = 256;

    k_zero_deg<<<(n + T - 1) / T, T>>>(n);
    k_degree<<<(E + T - 1) / T, T>>>(ei + (size_t)E, E, n);
    k_h_self<<<(n + T - 1) / T, T>>>((const float4*)x, W, b, (float4*)out, n);
    k_edge<<<(E + T - 1) / T, T>>>(ei, out, E, n);
}

// round 4
// speedup vs baseline: 1.1972x; 1.0552x over previous
#include <cuda_runtime.h>
#include <cuda_fp16.h>
#include <stdint.h>

#define N_NODES 1000000
#define F 16
#define MAX_E 4000000
#define SCAN_B 1024

// Scratch (allocation-free rule: __device__ globals)
__device__ __half g_h[(size_t)N_NODES * F];   // h = x @ W (fp16, 32MB)
__device__ float  g_dinv[N_NODES];            // rsqrt(deg + 1)
__device__ int    g_cnt[N_NODES];             // histogram, then scatter cursors
__device__ int    g_off[N_NODES + 1];         // CSR offsets (exclusive scan)
__device__ int    g_bsum[(N_NODES + SCAN_B - 1) / SCAN_B];
__device__ int    g_src[MAX_E];               // src ids grouped by dst

// ---------------------------------------------------------------------------
// K0: zero histogram
// ---------------------------------------------------------------------------
__global__ void k_zero(int n) {
    int i = blockIdx.x * blockDim.x + threadIdx.x;
    if (i < n) g_cnt[i] = 0;
}

// ---------------------------------------------------------------------------
// K1: histogram of dst (= degree without self loop). Int REDG, L2-resident.
// ---------------------------------------------------------------------------
__global__ void k_hist(const int* __restrict__ col, int E, int n) {
    int e = blockIdx.x * blockDim.x + threadIdx.x;
    if (e < E) {
        int c = col[e];
        if ((unsigned)c < (unsigned)n) atomicAdd(&g_cnt[c], 1);
    }
}

// ---------------------------------------------------------------------------
// K2a: per-block exclusive scan of g_cnt -> g_off, block totals -> g_bsum
// ---------------------------------------------------------------------------
__global__ void __launch_bounds__(SCAN_B)
k_scan_block(int n) {
    __shared__ int s[SCAN_B];
    int i = blockIdx.x * SCAN_B + threadIdx.x;
    int v = (i < n) ? g_cnt[i] : 0;
    s[threadIdx.x] = v;
    __syncthreads();
#pragma unroll
    for (int d = 1; d < SCAN_B; d <<= 1) {
        int t = (threadIdx.x >= d) ? s[threadIdx.x - d] : 0;
        __syncthreads();
        s[threadIdx.x] += t;
        __syncthreads();
    }
    if (i < n) g_off[i] = s[threadIdx.x] - v;   // exclusive
    if (threadIdx.x == SCAN_B - 1) g_bsum[blockIdx.x] = s[SCAN_B - 1];
}

// ---------------------------------------------------------------------------
// K2b: exclusive scan of block sums (single block; nb <= 1024)
// ---------------------------------------------------------------------------
__global__ void __launch_bounds__(SCAN_B)
k_scan_top(int nb) {
    __shared__ int s[SCAN_B];
    int v = (threadIdx.x < nb) ? g_bsum[threadIdx.x] : 0;
    s[threadIdx.x] = v;
    __syncthreads();
#pragma unroll
    for (int d = 1; d < SCAN_B; d <<= 1) {
        int t = (threadIdx.x >= d) ? s[threadIdx.x - d] : 0;
        __syncthreads();
        s[threadIdx.x] += t;
        __syncthreads();
    }
    if (threadIdx.x < nb) g_bsum[threadIdx.x] = s[threadIdx.x] - v;  // exclusive
}

// ---------------------------------------------------------------------------
// K2c: add block prefixes; compute dinv; write sentinel off[n]=E
// ---------------------------------------------------------------------------
__global__ void k_finish(int n, int E) {
    int i = blockIdx.x * blockDim.x + threadIdx.x;
    if (i < n) {
        g_off[i] += g_bsum[i / SCAN_B];
        g_dinv[i] = rsqrtf((float)g_cnt[i] + 1.0f);
    }
    if (i == 0) g_off[n] = E;
}

// ---------------------------------------------------------------------------
// K3: h = x @ W -> g_h (fp16). Pure streaming.
// ---------------------------------------------------------------------------
__global__ void __launch_bounds__(256)
k_h(const float4* __restrict__ x4, const float* __restrict__ W, int n) {
    __shared__ float sW[F * F];
    if (threadIdx.x < F * F) sW[threadIdx.x] = W[threadIdx.x];
    __syncthreads();

    int i = blockIdx.x * blockDim.x + threadIdx.x;
    if (i >= n) return;

    float4 xv0 = x4[(size_t)i * 4 + 0];
    float4 xv1 = x4[(size_t)i * 4 + 1];
    float4 xv2 = x4[(size_t)i * 4 + 2];
    float4 xv3 = x4[(size_t)i * 4 + 3];
    float xr[F] = {xv0.x, xv0.y, xv0.z, xv0.w,
                   xv1.x, xv1.y, xv1.z, xv1.w,
                   xv2.x, xv2.y, xv2.z, xv2.w,
                   xv3.x, xv3.y, xv3.z, xv3.w};

    float acc[F];
#pragma unroll
    for (int j = 0; j < F; j++) acc[j] = 0.0f;
#pragma unroll
    for (int k = 0; k < F; k++) {
        float xk = xr[k];
#pragma unroll
        for (int j = 0; j < F; j++) acc[j] = fmaf(xk, sW[k * F + j], acc[j]);
    }

    uint4 hpk[2];
    __half2* hh = reinterpret_cast<__half2*>(&hpk[0]);
#pragma unroll
    for (int q = 0; q < 8; q++)
        hh[q] = __floats2half2_rn(acc[2 * q], acc[2 * q + 1]);
    uint4* hp = reinterpret_cast<uint4*>(g_h + (size_t)i * F);
    hp[0] = hpk[0];
    hp[1] = hpk[1];
}

// ---------------------------------------------------------------------------
// K4: scatter src ids into dst-grouped buffer. Slot claimed by decrementing
// the histogram (ends at zero; k_zero re-zeroes next call anyway).
// ---------------------------------------------------------------------------
__global__ void k_scatter(const int* __restrict__ ei, int E, int n) {
    int e = blockIdx.x * blockDim.x + threadIdx.x;
    if (e >= E) return;
    int r = ei[e];
    int c = ei[(size_t)E + e];
    if ((unsigned)r >= (unsigned)n || (unsigned)c >= (unsigned)n) return;
    int k = atomicSub(&g_cnt[c], 1) - 1;   // unique slot 0..deg-1
    g_src[g_off[c] + k] = r;
}

// ---------------------------------------------------------------------------
// K5: per-dst gather + register accumulate + self loop + bias -> out.
// No atomics; out written once, coalesced.
// ---------------------------------------------------------------------------
__global__ void __launch_bounds__(256)
k_out(const float* __restrict__ b, float4* __restrict__ out4, int n) {
    __shared__ float sb[F];
    if (threadIdx.x < F) sb[threadIdx.x] = b[threadIdx.x];
    __syncthreads();

    int i = blockIdx.x * blockDim.x + threadIdx.x;
    if (i >= n) return;

    int s0 = g_off[i];
    int s1 = g_off[i + 1];
    float di = g_dinv[i];

    float acc[F];
#pragma unroll
    for (int j = 0; j < F; j++) acc[j] = 0.0f;

    for (int j = s0; j < s1; j++) {
        int s = __ldg(&g_src[j]);
        float ds = g_dinv[s];
        const uint4* hp = reinterpret_cast<const uint4*>(g_h + (size_t)s * F);
        uint4 p0 = __ldg(&hp[0]);
        uint4 p1 = __ldg(&hp[1]);
        const __half2* h0 = reinterpret_cast<const __half2*>(&p0);
        const __half2* h1 = reinterpret_cast<const __half2*>(&p1);
#pragma unroll
        for (int q = 0; q < 4; q++) {
            float2 f = __half22float2(h0[q]);
            acc[2 * q]     = fmaf(f.x, ds, acc[2 * q]);
            acc[2 * q + 1] = fmaf(f.y, ds, acc[2 * q + 1]);
        }
#pragma unroll
        for (int q = 0; q < 4; q++) {
            float2 f = __half22float2(h1[q]);
            acc[8 + 2 * q]     = fmaf(f.x, ds, acc[8 + 2 * q]);
            acc[8 + 2 * q + 1] = fmaf(f.y, ds, acc[8 + 2 * q + 1]);
        }
    }

    // self-loop term from fp16 h[i]
    float vi[F];
    {
        const uint4* hp = reinterpret_cast<const uint4*>(g_h + (size_t)i * F);
        uint4 p0 = hp[0];
        uint4 p1 = hp[1];
        const __half2* h0 = reinterpret_cast<const __half2*>(&p0);
        const __half2* h1 = reinterpret_cast<const __half2*>(&p1);
#pragma unroll
        for (int q = 0; q < 4; q++) {
            float2 f = __half22float2(h0[q]);
            vi[2 * q] = f.x; vi[2 * q + 1] = f.y;
            float2 g = __half22float2(h1[q]);
            vi[8 + 2 * q] = g.x; vi[8 + 2 * q + 1] = g.y;
        }
    }

    float dii = di * di;
#pragma unroll
    for (int q = 0; q < 4; q++) {
        out4[(size_t)i * 4 + q] = make_float4(
            fmaf(acc[q * 4 + 0], di, fmaf(vi[q * 4 + 0], dii, sb[q * 4 + 0])),
            fmaf(acc[q * 4 + 1], di, fmaf(vi[q * 4 + 1], dii, sb[q * 4 + 1])),
            fmaf(acc[q * 4 + 2], di, fmaf(vi[q * 4 + 2], dii, sb[q * 4 + 2])),
            fmaf(acc[q * 4 + 3], di, fmaf(vi[q * 4 + 3], dii, sb[q * 4 + 3])));
    }
}

// ---------------------------------------------------------------------------
// launch
// ---------------------------------------------------------------------------
extern "C" void kernel_launch(void* const* d_in, const int* in_sizes, int n_in,
                              void* d_out, int out_size) {
    const float* x   = (const float*)d_in[0];
    const int*   ei  = (const int*)d_in[1];  // int32 (JAX x64 disabled)
    const float* W   = (const float*)d_in[2];
    const float* b   = (const float*)d_in[3];
    float*       out = (float*)d_out;

    int n = in_sizes[0] / F;   // 1,000,000
    int E = in_sizes[1] / 2;   // 4,000,000
    if (E > MAX_E) E = MAX_E;

    const int T = 256;
    int nb = (n + SCAN_B - 1) / SCAN_B;

    k_zero<<<(n + T - 1) / T, T>>>(n);
    k_hist<<<(E + T - 1) / T, T>>>(ei + (size_t)E, E, n);
    k_scan_block<<<nb, SCAN_B>>>(n);
    k_scan_top<<<1, SCAN_B>>>(nb);
    k_finish<<<(n + T - 1) / T, T>>>(n, E);
    k_h<<<(n + T - 1) / T, T>>>((const float4*)x, W, n);
    k_scatter<<<(E + T - 1) / T, T>>>(ei, E, n);
    k_out<<<(n + T - 1) / T, T>>>(b, (float4*)out, n);
}